// round 11
// baseline (speedup 1.0000x reference)
#include <cuda_runtime.h>
#include <cuda_fp16.h>

typedef unsigned int u32;
typedef unsigned long long u64;

#define BB 4
#define TT 16
#define HH 64
#define WW 64
#define FF 64
#define HW 4096
#define HW3 1024

#define LOSCALE 2048.0f
#define LOSCALE_INV 4.8828125e-4f

// Scratch (device globals). xz is stored in the gate-interleaved PERMUTED
// layout: column pcol = feature*4 + gate(i,f,c,o).
__device__ float g_xz[(long long)BB*TT*HW*256];
__device__ float g_ha[(long long)BB*TT*HW*FF];   // layer-1 h
__device__ float g_hb[(long long)BB*TT*HW*FF];   // layer-2 h
__device__ float g_h3[(long long)BB*TT*HW3*FF];  // layer-3 h
__device__ float g_c [(long long)BB*HW*FF];
__device__ u32   g_wb32[843776];   // packed fp16 hi/lo weight fragments
__device__ float g_pb[768];        // permuted biases
__device__ int   g_bar[64];        // software grid-barrier slots

__device__ __forceinline__ float hsg(float x){ return fminf(fmaxf(fmaf(x,0.2f,0.5f),0.f),1.f); }
__device__ __forceinline__ u32 smem_u32(const void* p){
    u32 a;
    asm("{ .reg .u64 t; cvta.to.shared.u64 t, %1; cvt.u32.u64 %0, t; }":"=r"(a):"l"(p));
    return a;
}
__device__ __forceinline__ void cpa16(u32 s, const void* g){
    asm volatile("cp.async.cg.shared.global [%0], [%1], 16;"::"r"(s),"l"(g));
}
#define CP_COMMIT() asm volatile("cp.async.commit_group;")
#define CP_WAIT0()  asm volatile("cp.async.wait_group 0;" ::: "memory")
__device__ __forceinline__ void ldm4(u32* r, u32 a){
    asm volatile("ldmatrix.sync.aligned.m8n8.x4.shared.b16 {%0,%1,%2,%3}, [%4];"
        :"=r"(r[0]),"=r"(r[1]),"=r"(r[2]),"=r"(r[3]):"r"(a));
}
// fp16 operands, fp32 accum (main hh term)
__device__ __forceinline__ void mma_f32(float* c, const u32* a, u32 b0, u32 b1){
    asm volatile("mma.sync.aligned.m16n8k16.row.col.f32.f16.f16.f32 "
        "{%0,%1,%2,%3}, {%4,%5,%6,%7}, {%8,%9}, {%0,%1,%2,%3};"
        : "+f"(c[0]),"+f"(c[1]),"+f"(c[2]),"+f"(c[3])
        : "r"(a[0]),"r"(a[1]),"r"(a[2]),"r"(a[3]),"r"(b0),"r"(b1));
}
// fp16 operands, fp16 accum (correction terms, hypothesized 2x rate)
__device__ __forceinline__ void mma_f16(u32* c, const u32* a, u32 b0, u32 b1){
    asm volatile("mma.sync.aligned.m16n8k16.row.col.f16.f16.f16.f16 "
        "{%0,%1}, {%2,%3,%4,%5}, {%6,%7}, {%0,%1};"
        : "+r"(c[0]),"+r"(c[1])
        : "r"(a[0]),"r"(a[1]),"r"(a[2]),"r"(a[3]),"r"(b0),"r"(b1));
}
// 16 fp32 -> 8 hi fp16x2 + 8 scaled-lo fp16x2
__device__ __forceinline__ void cvt16(const float* v, u32* c){
    #pragma unroll
    for (int e=0;e<8;e++){
        __half h0=__float2half_rn(v[2*e]),   h1=__float2half_rn(v[2*e+1]);
        __half l0=__float2half_rn((v[2*e]  -__half2float(h0))*LOSCALE);
        __half l1=__float2half_rn((v[2*e+1]-__half2float(h1))*LOSCALE);
        union { __half2 b; u32 x; } ph, pl;
        ph.b = __half2(h0,h1); pl.b = __half2(l0,l1);
        c[e]=ph.x; c[8+e]=pl.x;
    }
}

// ---------------------------------------------------------------------------
// Weight prep: fp32 (K x 256, cols i|f|c|o x 64) -> per-32k-chunk fp16 hi/lo
// B-fragment images for mma.m16n8k16, columns permuted to pcol = f*4+g.
// ---------------------------------------------------------------------------
__device__ __forceinline__ void prep_one(const float* __restrict__ w,
                                         u32* __restrict__ dst, int K, int idx)
{
    int chunk = idx >> 12, r = idx & 4095;
    int k16 = r >> 11, t = r & 2047;
    int nt = t >> 6, u = t & 63;
    int lane = u >> 1, reg = u & 1;
    int pcol = nt*8 + (lane>>2);
    int f = pcol >> 2, g = pcol & 3;
    int n_orig = g*64 + f;
    int kg = chunk*32 + k16*16 + reg*8 + (lane&3)*2;
    float v0 = (kg   < K) ? w[(long long)kg*256 + n_orig] : 0.f;
    float v1 = (kg+1 < K) ? w[(long long)(kg+1)*256 + n_orig] : 0.f;
    __half h0 = __float2half_rn(v0), h1 = __float2half_rn(v1);
    __half l0 = __float2half_rn((v0 - __half2float(h0))*LOSCALE);
    __half l1 = __float2half_rn((v1 - __half2float(h1))*LOSCALE);
    union { __half2 b; u32 x; } ph, pl;
    ph.b = __half2(h0, h1);
    pl.b = __half2(l0, l1);
    dst[(long long)chunk*8192 + r]        = ph.x;
    dst[(long long)chunk*8192 + 4096 + r] = pl.x;
}

#define O1K 0
#define O1R 106496
#define O2K 516096
#define O2R 663552
#define O3K 811008
#define O3R 827392

__global__ void prep_all(const float* k1, const float* rk1, const float* k2,
                         const float* rk2, const float* k3, const float* rk3,
                         u32* __restrict__ wb)
{
    int gid = blockIdx.x*256 + threadIdx.x;
    if (gid >= 103*4096) return;
    int cg = gid >> 12;
    const float* w; u32* dst; int K, base;
    if      (cg < 13) { w = k1;  dst = wb+O1K; K = 400;  base = 0;   }
    else if (cg < 63) { w = rk1; dst = wb+O1R; K = 1600; base = 13;  }
    else if (cg < 81) { w = k2;  dst = wb+O2K; K = 576;  base = 63;  }
    else if (cg < 99) { w = rk2; dst = wb+O2R; K = 576;  base = 81;  }
    else if (cg < 101){ w = k3;  dst = wb+O3K; K = 64;   base = 99;  }
    else              { w = rk3; dst = wb+O3R; K = 64;   base = 101; }
    prep_one(w, dst, K, gid - base*4096);
}

__global__ void prep_misc(const float* b1, const float* b2, const float* b3,
                          float* __restrict__ pb)
{
    int i = threadIdx.x + blockIdx.x*256;
    if (i < 64) g_bar[i] = 0;
    if (i < 768){
        int l = i >> 8, pcol = i & 255;
        const float* b = (l==0) ? b1 : ((l==1) ? b2 : b3);
        pb[i] = b[(pcol&3)*64 + (pcol>>2)];
    }
}

#define STG_BYTES 53248
#define SMEM_TOT  106496

// shared compute body: hh in f32 accum, corrections in f16 accum drained with
// a scaled FMA into the f32 accumulators (fma pipe is idle).
#define COMPUTE_BODY(Ab, Bb) \
    _Pragma("unroll") \
    for (int k16=0;k16<2;k16++){ \
        u32 ah[4][4], al[4][4]; \
        _Pragma("unroll") \
        for (int mt=0;mt<4;mt++){ \
            u32 ra = (Ab) + (wm*64+mt*16)*80 + ldm_off + k16*32; \
            ldm4(ah[mt], ra); \
            ldm4(al[mt], ra + 10240); \
        } \
        _Pragma("unroll") \
        for (int nt=0;nt<8;nt++){ \
            int off = ((k16*32 + wn*8 + nt)*64 + lane*2)*4; \
            uint2 bh = *(const uint2*)((Bb) + off); \
            uint2 bl = *(const uint2*)((Bb) + 16384 + off); \
            _Pragma("unroll") \
            for (int mt=0;mt<4;mt++) \
                mma_f32(acc[mt][nt], ah[mt], bh.x, bh.y); \
            _Pragma("unroll") \
            for (int mt=0;mt<4;mt++){ \
                u32 c16[2]; c16[0]=0u; c16[1]=0u; \
                mma_f16(c16, al[mt], bh.x, bh.y); \
                mma_f16(c16, ah[mt], bl.x, bl.y); \
                __half2 d0 = *(__half2*)&c16[0]; \
                __half2 d1 = *(__half2*)&c16[1]; \
                acc[mt][nt][0] = fmaf(__half2float(d0.x), LOSCALE_INV, acc[mt][nt][0]); \
                acc[mt][nt][1] = fmaf(__half2float(d0.y), LOSCALE_INV, acc[mt][nt][1]); \
                acc[mt][nt][2] = fmaf(__half2float(d1.x), LOSCALE_INV, acc[mt][nt][2]); \
                acc[mt][nt][3] = fmaf(__half2float(d1.y), LOSCALE_INV, acc[mt][nt][3]); \
            } \
        } \
    }

// ===========================================================================
// Input conv. BM=128, BN=256, BK=32, 256 threads (8 warps, wm2 x wn4),
// warp tile 64x64. fp16 hi/lo split (scaled lo). Fused gate0 for t==0.
// ===========================================================================
template<int KH, int STRIDE, int CIN, bool HASBN>
__global__ void __launch_bounds__(256, 1)
conv_in(const float* __restrict__ in, long long in_str,
        const u32* __restrict__ wch, int NC,
        const float* __restrict__ biasP,
        const float* __restrict__ bns, const float* __restrict__ bnb,
        float* __restrict__ cbuf,
        float* __restrict__ outp, long long out_str,
        float* __restrict__ h0out, long long h0_str,
        int Hin, int Win, int Ho, int Wo)
{
    constexpr int PAD = (KH-1)/2;
    extern __shared__ char smem[];
    const u32 sb = smem_u32(smem);
    const int tid = threadIdx.x, wid = tid>>5, lane = tid&31;
    const int wm = wid>>2, wn = wid&3;
    const int HoWo = Ho*Wo;
    const int mblk = blockIdx.x << 7;

    const int arow = tid & 127, khalf = tid >> 7;
    const int am = mblk + arow;
    const int aimg = am / HoWo;
    const int ap = am - aimg*HoWo;
    const int oy = ap / Wo, ox = ap - (ap/Wo)*Wo;
    const float* inp = in + (long long)aimg*in_str;

    const int ldm_off = ((lane&7) + ((lane>>3)&1)*8)*80 + (lane>>4)*16;

    float acc[4][8][4];
    #pragma unroll
    for (int i=0;i<4;i++)
        #pragma unroll
        for (int j=0;j<8;j++)
            #pragma unroll
            for (int k=0;k<4;k++) acc[i][j][k]=0.f;

    auto gather = [&](int ic, float* v){
        #pragma unroll
        for (int e=0;e<16;e++) v[e]=0.f;
        const int kg = ic*32 + khalf*16;
        const int tap = kg / CIN;
        if (tap < KH*KH){
            const int ci = kg % CIN;
            const int ky = tap / KH, kx = tap - (tap/KH)*KH;
            const int iy = oy*STRIDE + ky - PAD;
            const int ix = ox*STRIDE + kx - PAD;
            if ((unsigned)iy < (unsigned)Hin && (unsigned)ix < (unsigned)Win){
                const float4* sp = (const float4*)(inp + ((long long)iy*Win+ix)*CIN + ci);
                #pragma unroll
                for (int q=0;q<4;q++){
                    float4 a = sp[q];
                    v[q*4+0]=a.x; v[q*4+1]=a.y; v[q*4+2]=a.z; v[q*4+3]=a.w;
                }
                if (HASBN){
                    const float BNRS = 0.9995003746877732f;
                    #pragma unroll
                    for (int e=0;e<16;e++)
                        v[e] = fmaf(v[e], __ldg(bns+ci+e)*BNRS, __ldg(bnb+ci+e));
                }
            }
        }
    };
    auto storeAc = [&](int s, const u32* c){
        char* base = smem + s*STG_BYTES + arow*80 + khalf*32;
        *(uint4*)base             = make_uint4(c[0],c[1],c[2],c[3]);
        *(uint4*)(base+16)        = make_uint4(c[4],c[5],c[6],c[7]);
        *(uint4*)(base+10240)     = make_uint4(c[8],c[9],c[10],c[11]);
        *(uint4*)(base+10240+16)  = make_uint4(c[12],c[13],c[14],c[15]);
    };
    auto copyB = [&](int ic, int s){
        const char* src = (const char*)(wch + (long long)ic*8192);
        u32 dstb = sb + s*STG_BYTES + 20480;
        #pragma unroll
        for (int i=0;i<8;i++)
            cpa16(dstb + tid*16 + i*4096, src + tid*16 + i*4096);
        CP_COMMIT();
    };

    u32 ca[16];
    {
        float v[16];
        gather(0, v); cvt16(v, ca);
        storeAc(0, ca);
        copyB(0, 0);
        CP_WAIT0();
        __syncthreads();
    }
    for (int ic=0; ic<NC; ic++){
        const int s = ic & 1;
        const bool more = (ic+1 < NC);
        float v[16];
        if (more){ copyB(ic+1, s^1); gather(ic+1, v); }
        {
            const u32 Ab = sb + s*STG_BYTES;
            const char* Bb = smem + s*STG_BYTES + 20480;
            COMPUTE_BODY(Ab, Bb)
        }
        if (more){ cvt16(v, ca); storeAc(s^1, ca); CP_WAIT0(); }
        __syncthreads();
    }

    // epilogue via SMEM (two 64-row halves)
    float* zsm = (float*)smem;   // [64][264]
    #pragma unroll
    for (int half=0; half<2; half++){
        if (wm == half){
            #pragma unroll
            for (int mt=0;mt<4;mt++){
                #pragma unroll
                for (int nt=0;nt<8;nt++){
                    int row = mt*16 + (lane>>2);
                    int col = wn*64 + nt*8 + (lane&3)*2;
                    *(float2*)&zsm[row*264 + col]     = make_float2(acc[mt][nt][0], acc[mt][nt][1]);
                    *(float2*)&zsm[(row+8)*264 + col] = make_float2(acc[mt][nt][2], acc[mt][nt][3]);
                }
            }
        }
        __syncthreads();
        {
            const int row = tid >> 2, fq = tid & 3;
            const int m = mblk + half*64 + row;
            const int img = m / HoWo;
            const int pix = m - img*HoWo;
            float* op = outp + (long long)img*out_str + (long long)pix*256 + fq*64;
            float4 o[16];
            #pragma unroll
            for (int j=0;j<16;j++){
                float4 q = *(float4*)&zsm[row*264 + fq*64 + j*4];
                float4 bv = *(const float4*)(biasP + fq*64 + j*4);
                o[j] = make_float4(q.x+bv.x, q.y+bv.y, q.z+bv.z, q.w+bv.w);
                *(float4*)(op + j*4) = o[j];
            }
            if ((img & 15) == 0){
                const int b = img >> 4;
                float cn[16], ho[16];
                #pragma unroll
                for (int j=0;j<16;j++){
                    float c = hsg(o[j].x)*fmaxf(o[j].z, 0.f);
                    cn[j] = c;
                    ho[j] = hsg(o[j].w)*fmaxf(c, 0.f);
                }
                float* cp = cbuf + ((long long)b*HoWo + pix)*64 + fq*16;
                float* hp = h0out + (long long)b*h0_str + (long long)pix*64 + fq*16;
                #pragma unroll
                for (int g=0; g<4; g++){
                    *(float4*)(cp + g*4) = *(float4*)&cn[g*4];
                    *(float4*)(hp + g*4) = *(float4*)&ho[g*4];
                }
            }
        }
        __syncthreads();
    }
}

// ===========================================================================
// Persistent recurrent conv (same tiling), software grid barrier per step.
// ===========================================================================
template<int KH, int CIN>
__global__ void __launch_bounds__(256, 1)
conv_rec(const float* __restrict__ hbuf, long long H_Tp, long long H_IMGp,
         const u32* __restrict__ wch, int NC,
         const float* __restrict__ xzb, long long XZ_Tp, long long XZ_IMGp,
         float* __restrict__ cbuf, int nstep, int barbase, int Ho, int Wo)
{
    constexpr int PAD = (KH-1)/2;
    extern __shared__ char smem[];
    const u32 sb = smem_u32(smem);
    const int tid = threadIdx.x, wid = tid>>5, lane = tid&31;
    const int wm = wid>>2, wn = wid&3;
    const int HoWo = Ho*Wo;
    const int mblk = blockIdx.x << 7;
    const int nblk = gridDim.x;

    const int arow = tid & 127, khalf = tid >> 7;
    const int am = mblk + arow;
    const int aimg = am / HoWo;
    const int ap = am - aimg*HoWo;
    const int oy = ap / Wo, ox = ap - (ap/Wo)*Wo;

    const int ldm_off = ((lane&7) + ((lane>>3)&1)*8)*80 + (lane>>4)*16;
    const int erow = tid >> 2, efq = tid & 3;

    for (int t = 1; t <= nstep; t++){
        const float* inp = hbuf + (long long)(t-1)*H_Tp + (long long)aimg*H_IMGp;

        float acc[4][8][4];
        #pragma unroll
        for (int i=0;i<4;i++)
            #pragma unroll
            for (int j=0;j<8;j++)
                #pragma unroll
                for (int k=0;k<4;k++) acc[i][j][k]=0.f;

        auto gather = [&](int ic, float* v){
            #pragma unroll
            for (int e=0;e<16;e++) v[e]=0.f;
            const int kg = ic*32 + khalf*16;
            const int tap = kg / CIN;
            if (tap < KH*KH){
                const int ci = kg % CIN;
                const int ky = tap / KH, kx = tap - (tap/KH)*KH;
                const int iy = oy + ky - PAD;
                const int ix = ox + kx - PAD;
                if ((unsigned)iy < (unsigned)Ho && (unsigned)ix < (unsigned)Wo){
                    const float4* sp = (const float4*)(inp + ((long long)iy*Wo+ix)*CIN + ci);
                    #pragma unroll
                    for (int q=0;q<4;q++){
                        float4 a = sp[q];
                        v[q*4+0]=a.x; v[q*4+1]=a.y; v[q*4+2]=a.z; v[q*4+3]=a.w;
                    }
                }
            }
        };
        auto storeAc = [&](int s, const u32* c){
            char* base = smem + s*STG_BYTES + arow*80 + khalf*32;
            *(uint4*)base             = make_uint4(c[0],c[1],c[2],c[3]);
            *(uint4*)(base+16)        = make_uint4(c[4],c[5],c[6],c[7]);
            *(uint4*)(base+10240)     = make_uint4(c[8],c[9],c[10],c[11]);
            *(uint4*)(base+10240+16)  = make_uint4(c[12],c[13],c[14],c[15]);
        };
        auto copyB = [&](int ic, int s){
            const char* src = (const char*)(wch + (long long)ic*8192);
            u32 dstb = sb + s*STG_BYTES + 20480;
            #pragma unroll
            for (int i=0;i<8;i++)
                cpa16(dstb + tid*16 + i*4096, src + tid*16 + i*4096);
            CP_COMMIT();
        };

        u32 ca[16];
        {
            float v[16];
            gather(0, v); cvt16(v, ca);
            storeAc(0, ca);
            copyB(0, 0);
            CP_WAIT0();
            __syncthreads();
        }
        for (int ic=0; ic<NC; ic++){
            const int s = ic & 1;
            const bool more = (ic+1 < NC);
            float v[16];
            if (more){ copyB(ic+1, s^1); gather(ic+1, v); }
            {
                const u32 Ab = sb + s*STG_BYTES;
                const char* Bb = smem + s*STG_BYTES + 20480;
                COMPUTE_BODY(Ab, Bb)
            }
            if (more){ cvt16(v, ca); storeAc(s^1, ca); CP_WAIT0(); }
            __syncthreads();
        }

        // epilogue
        float* zsm = (float*)smem;
        #pragma unroll
        for (int half=0; half<2; half++){
            if (wm == half){
                #pragma unroll
                for (int mt=0;mt<4;mt++){
                    #pragma unroll
                    for (int nt=0;nt<8;nt++){
                        int row = mt*16 + (lane>>2);
                        int col = wn*64 + nt*8 + (lane&3)*2;
                        *(float2*)&zsm[row*264 + col]     = make_float2(acc[mt][nt][0], acc[mt][nt][1]);
                        *(float2*)&zsm[(row+8)*264 + col] = make_float2(acc[mt][nt][2], acc[mt][nt][3]);
                    }
                }
            }
            __syncthreads();
            {
                const int m = mblk + half*64 + erow;
                const int img = m / HoWo;
                const int pix = m - img*HoWo;
                const float* za = xzb + (long long)t*XZ_Tp + (long long)img*XZ_IMGp
                                  + (long long)pix*256 + efq*64;
                float* cp = cbuf + ((long long)img*HoWo + pix)*64 + efq*16;
                float* hp = (float*)(hbuf + (long long)t*H_Tp + (long long)img*H_IMGp
                                     + (long long)pix*64 + efq*16);
                float co[16], cn[16], ho[16];
                #pragma unroll
                for (int g=0; g<4; g++)
                    *(float4*)&co[g*4] = *(const float4*)(cp + g*4);
                #pragma unroll
                for (int j=0;j<16;j++){
                    float4 q = *(float4*)&zsm[erow*264 + efq*64 + j*4];
                    float4 x = *(const float4*)(za + j*4);
                    float zi = q.x + x.x, zf = q.y + x.y;
                    float zc = q.z + x.z, zo = q.w + x.w;
                    float c = hsg(zf)*co[j] + hsg(zi)*fmaxf(zc,0.f);
                    cn[j] = c; ho[j] = hsg(zo)*fmaxf(c,0.f);
                }
                #pragma unroll
                for (int g=0; g<4; g++){
                    *(float4*)(cp + g*4) = *(float4*)&cn[g*4];
                    *(float4*)(hp + g*4) = *(float4*)&ho[g*4];
                }
            }
            __syncthreads();
        }

        if (t < nstep){
            __threadfence();
            __syncthreads();
            if (tid == 0){
                int* bp = &g_bar[barbase + t];
                atomicAdd(bp, 1);
                u32 v;
                do {
                    asm volatile("ld.acquire.gpu.global.u32 %0, [%1];"
                                 : "=r"(v) : "l"(bp) : "memory");
                    if (v < (u32)nblk) __nanosleep(128);
                } while (v < (u32)nblk);
            }
            __syncthreads();
        }
    }
}

// ---------------------------------------------------------------------------
// Conv3D 3x3x3 64->1 SAME + ReLU
// ---------------------------------------------------------------------------
__global__ void conv3d_kernel(const float* __restrict__ h, const float* __restrict__ w,
                              const float* __restrict__ b, float* __restrict__ out)
{
    const int idx = blockIdx.x*256 + threadIdx.x;
    if (idx >= BB*TT*32*32) return;
    const int x = idx & 31, y = (idx >> 5) & 31, t = (idx >> 10) & 15, bb = idx >> 14;
    float acc = __ldg(&b[0]);
    #pragma unroll
    for (int dt=-1; dt<=1; dt++){
        const int ti = t + dt;
        if ((unsigned)ti >= (unsigned)TT) continue;
        #pragma unroll
        for (int dy=-1; dy<=1; dy++){
            const int yi = y + dy;
            if ((unsigned)yi >= 32u) continue;
            #pragma unroll
            for (int dx=-1; dx<=1; dx++){
                const int xi = x + dx;
                if ((unsigned)xi >= 32u) continue;
                const float4* hp = (const float4*)(h + ((((long long)bb*TT+ti)*32+yi)*32+xi)*FF);
                const float4* wp = (const float4*)(w + (((dt+1)*3+(dy+1))*3+(dx+1))*FF);
                #pragma unroll
                for (int c4=0;c4<16;c4++){
                    float4 hv = hp[c4], wv = __ldg(&wp[c4]);
                    acc += hv.x*wv.x + hv.y*wv.y + hv.z*wv.z + hv.w*wv.w;
                }
            }
        }
    }
    out[idx] = fmaxf(acc, 0.f);
}

// ---------------------------------------------------------------------------
// Host
// ---------------------------------------------------------------------------
extern "C" void kernel_launch(void* const* d_in, const int* in_sizes, int n_in,
                              void* d_out, int out_size)
{
    const float* x   = (const float*)d_in[0];
    const float* k1  = (const float*)d_in[1];
    const float* rk1 = (const float*)d_in[2];
    const float* b1  = (const float*)d_in[3];
    const float* g1  = (const float*)d_in[4];
    const float* be1 = (const float*)d_in[5];
    const float* k2  = (const float*)d_in[6];
    const float* rk2 = (const float*)d_in[7];
    const float* b2  = (const float*)d_in[8];
    const float* g2  = (const float*)d_in[9];
    const float* be2 = (const float*)d_in[10];
    const float* k3  = (const float*)d_in[11];
    const float* rk3 = (const float*)d_in[12];
    const float* b3  = (const float*)d_in[13];
    const float* w3d = (const float*)d_in[14];
    const float* b3d = (const float*)d_in[15];
    float* out = (float*)d_out;

    float *xz, *ha, *hb, *h3, *cc, *pb;
    u32* wb;
    cudaGetSymbolAddress((void**)&xz, g_xz);
    cudaGetSymbolAddress((void**)&ha, g_ha);
    cudaGetSymbolAddress((void**)&hb, g_hb);
    cudaGetSymbolAddress((void**)&h3, g_h3);
    cudaGetSymbolAddress((void**)&cc, g_c);
    cudaGetSymbolAddress((void**)&wb, g_wb32);
    cudaGetSymbolAddress((void**)&pb, g_pb);

    auto* f1i = conv_in<5,1,16,false>;
    auto* f2i = conv_in<3,1,64,true>;
    auto* f3i = conv_in<1,2,64,true>;
    auto* r1  = conv_rec<5,64>;
    auto* r2  = conv_rec<3,64>;
    auto* r3  = conv_rec<1,64>;
    cudaFuncSetAttribute(f1i, cudaFuncAttributeMaxDynamicSharedMemorySize, SMEM_TOT);
    cudaFuncSetAttribute(f2i, cudaFuncAttributeMaxDynamicSharedMemorySize, SMEM_TOT);
    cudaFuncSetAttribute(f3i, cudaFuncAttributeMaxDynamicSharedMemorySize, SMEM_TOT);
    cudaFuncSetAttribute(r1,  cudaFuncAttributeMaxDynamicSharedMemorySize, SMEM_TOT);
    cudaFuncSetAttribute(r2,  cudaFuncAttributeMaxDynamicSharedMemorySize, SMEM_TOT);
    cudaFuncSetAttribute(r3,  cudaFuncAttributeMaxDynamicSharedMemorySize, SMEM_TOT);

    const long long X_IMG = (long long)HW*16;
    const long long XZ_IMG = (long long)TT*HW*256, XZ_T = (long long)HW*256;
    const long long H_IMG = (long long)TT*HW*FF,   H_T  = (long long)HW*FF;
    const long long XZ3_IMG = (long long)TT*HW3*256, XZ3_T = (long long)HW3*256;
    const long long H3_IMG = (long long)TT*HW3*FF,   H3_T  = (long long)HW3*FF;

    // Launch order keeps the profiler (local launch index 3) on r1.
    prep_all<<<1648, 256>>>(k1, rk1, k2, rk2, k3, rk3, wb);        // 0
    prep_misc<<<3, 256>>>(b1, b2, b3, pb);                         // 1

    // ============ Layer 1: ConvLSTM 5x5 ============
    f1i<<<2048, 256, SMEM_TOT>>>(x, X_IMG, wb+O1K, 13, pb,         // 2
        nullptr, nullptr, cc, xz, XZ_T, ha, H_IMG, HH, WW, HH, WW);
    r1<<<128, 256, SMEM_TOT>>>(ha, H_T, H_IMG, wb+O1R, 50,         // 3 <- profiled
        xz, XZ_T, XZ_IMG, cc, 15, 0, HH, WW);

    // ============ Layer 2: ConvLSTM 3x3 (BN1 folded) ============
    f2i<<<2048, 256, SMEM_TOT>>>(ha, H_T, wb+O2K, 18, pb+256,
        g1, be1, cc, xz, XZ_T, hb, H_IMG, HH, WW, HH, WW);
    r2<<<128, 256, SMEM_TOT>>>(hb, H_T, H_IMG, wb+O2R, 18,
        xz, XZ_T, XZ_IMG, cc, 15, 16, HH, WW);

    // ============ Layer 3: ConvLSTM 1x1 stride 2 (BN2 folded) ============
    f3i<<<512, 256, SMEM_TOT>>>(hb, H_T, wb+O3K, 2, pb+512,
        g2, be2, cc, xz, XZ3_T, h3, H3_IMG, HH, WW, 32, 32);
    r3<<<32, 256, SMEM_TOT>>>(h3, H3_T, H3_IMG, wb+O3R, 2,
        xz, XZ3_T, XZ3_IMG, cc, 15, 32, 32, 32);

    conv3d_kernel<<<256, 256>>>(h3, w3d, b3d, out);
}

// round 12
// speedup vs baseline: 1.0702x; 1.0702x over previous
#include <cuda_runtime.h>
#include <cuda_fp16.h>

typedef unsigned int u32;
typedef unsigned long long u64;
typedef long long ll;

#define BB 4
#define TT 16
#define HH 64
#define WW 64
#define FF 64
#define HW 4096
#define HW3 1024

// Scratch (device globals). xz is stored in the gate-interleaved PERMUTED
// layout: column pcol = feature*4 + gate(i,f,c,o).
__device__ float g_xz[(long long)BB*TT*HW*256];
__device__ float g_ha[(long long)BB*TT*HW*FF];   // layer-1 h
__device__ float g_hb[(long long)BB*TT*HW*FF];   // layer-2 h
__device__ float g_h3[(long long)BB*TT*HW3*FF];  // layer-3 h
__device__ float g_c [(long long)BB*HW*FF];
__device__ u32   g_wb32[843776];   // packed fp16 hi/lo weight fragments
__device__ float g_pb[768];        // permuted biases
__device__ int   g_flag[4352];     // per (t,tile) done flags: r1@0, r2@1920, r3@3840
__device__ int   g_ctr[4];         // work-steal counters

__device__ __forceinline__ float hsg(float x){ return fminf(fmaxf(fmaf(x,0.2f,0.5f),0.f),1.f); }
__device__ __forceinline__ u32 smem_u32(const void* p){
    u32 a;
    asm("{ .reg .u64 t; cvta.to.shared.u64 t, %1; cvt.u32.u64 %0, t; }":"=r"(a):"l"(p));
    return a;
}
__device__ __forceinline__ void cpa16(u32 s, const void* g){
    asm volatile("cp.async.cg.shared.global [%0], [%1], 16;"::"r"(s),"l"(g));
}
#define CP_COMMIT() asm volatile("cp.async.commit_group;")
#define CP_WAIT0()  asm volatile("cp.async.wait_group 0;" ::: "memory")
__device__ __forceinline__ void ldm4(u32* r, u32 a){
    asm volatile("ldmatrix.sync.aligned.m8n8.x4.shared.b16 {%0,%1,%2,%3}, [%4];"
        :"=r"(r[0]),"=r"(r[1]),"=r"(r[2]),"=r"(r[3]):"r"(a));
}
// fp16 operands, fp32 accum
__device__ __forceinline__ void mma_f32(float* c, const u32* a, u32 b0, u32 b1){
    asm volatile("mma.sync.aligned.m16n8k16.row.col.f32.f16.f16.f32 "
        "{%0,%1,%2,%3}, {%4,%5,%6,%7}, {%8,%9}, {%0,%1,%2,%3};"
        : "+f"(c[0]),"+f"(c[1]),"+f"(c[2]),"+f"(c[3])
        : "r"(a[0]),"r"(a[1]),"r"(a[2]),"r"(a[3]),"r"(b0),"r"(b1));
}
// 16 fp32 -> 8 hi fp16x2 + 8 lo fp16x2 (unscaled residual)
__device__ __forceinline__ void cvt16(const float* v, u32* c){
    #pragma unroll
    for (int e=0;e<8;e++){
        __half h0=__float2half_rn(v[2*e]),   h1=__float2half_rn(v[2*e+1]);
        __half l0=__float2half_rn(v[2*e]  -__half2float(h0));
        __half l1=__float2half_rn(v[2*e+1]-__half2float(h1));
        union { __half2 b; u32 x; } ph, pl;
        ph.b = __half2(h0,h1); pl.b = __half2(l0,l1);
        c[e]=ph.x; c[8+e]=pl.x;
    }
}
__device__ __forceinline__ float ldcg(const float* p){
    float v; asm volatile("ld.global.cg.f32 %0, [%1];" : "=f"(v) : "l"(p)); return v;
}
__device__ __forceinline__ void stcg(float* p, float v){
    asm volatile("st.global.cg.f32 [%0], %1;" :: "l"(p), "f"(v));
}

// ---------------------------------------------------------------------------
// Weight prep: fp32 (K x 256, cols i|f|c|o x 64) -> per-32k-chunk fp16 hi/lo
// B-fragment images for mma.m16n8k16, columns permuted to pcol = f*4+g.
// ---------------------------------------------------------------------------
__device__ __forceinline__ void prep_one(const float* __restrict__ w,
                                         u32* __restrict__ dst, int K, int idx)
{
    int chunk = idx >> 12, r = idx & 4095;
    int k16 = r >> 11, t = r & 2047;
    int nt = t >> 6, u = t & 63;
    int lane = u >> 1, reg = u & 1;
    int pcol = nt*8 + (lane>>2);
    int f = pcol >> 2, g = pcol & 3;
    int n_orig = g*64 + f;
    int kg = chunk*32 + k16*16 + reg*8 + (lane&3)*2;
    float v0 = (kg   < K) ? w[(ll)kg*256 + n_orig] : 0.f;
    float v1 = (kg+1 < K) ? w[(ll)(kg+1)*256 + n_orig] : 0.f;
    __half h0 = __float2half_rn(v0), h1 = __float2half_rn(v1);
    __half l0 = __float2half_rn(v0 - __half2float(h0));
    __half l1 = __float2half_rn(v1 - __half2float(h1));
    union { __half2 b; u32 x; } ph, pl;
    ph.b = __half2(h0, h1);
    pl.b = __half2(l0, l1);
    dst[(ll)chunk*8192 + r]        = ph.x;
    dst[(ll)chunk*8192 + 4096 + r] = pl.x;
}

#define O1K 0
#define O1R 106496
#define O2K 516096
#define O2R 663552
#define O3K 811008
#define O3R 827392

__global__ void prep_all(const float* k1, const float* rk1, const float* k2,
                         const float* rk2, const float* k3, const float* rk3,
                         u32* __restrict__ wb)
{
    int gid = blockIdx.x*256 + threadIdx.x;
    if (gid >= 103*4096) return;
    int cg = gid >> 12;
    const float* w; u32* dst; int K, base;
    if      (cg < 13) { w = k1;  dst = wb+O1K; K = 400;  base = 0;   }
    else if (cg < 63) { w = rk1; dst = wb+O1R; K = 1600; base = 13;  }
    else if (cg < 81) { w = k2;  dst = wb+O2K; K = 576;  base = 63;  }
    else if (cg < 99) { w = rk2; dst = wb+O2R; K = 576;  base = 81;  }
    else if (cg < 101){ w = k3;  dst = wb+O3K; K = 64;   base = 99;  }
    else              { w = rk3; dst = wb+O3R; K = 64;   base = 101; }
    prep_one(w, dst, K, gid - base*4096);
}

// zero flags/counters + permuted biases
__global__ void prep_misc(const float* b1, const float* b2, const float* b3,
                          float* __restrict__ pb)
{
    int i = threadIdx.x + blockIdx.x*256;
    if (i < 4352) g_flag[i] = 0;
    if (i < 4)    g_ctr[i]  = 0;
    if (i < 768){
        int l = i >> 8, pcol = i & 255;
        const float* b = (l==0) ? b1 : ((l==1) ? b2 : b3);
        pb[i] = b[(pcol&3)*64 + (pcol>>2)];
    }
}

#define STG_BYTES 53248
#define SMEM_TOT  106512   // 2 stages + 16B control word

// shared compute body (fp16x3, fp32 accum)
#define COMPUTE_BODY(Ab, Bb) \
    _Pragma("unroll") \
    for (int k16=0;k16<2;k16++){ \
        u32 ah[4][4], al[4][4]; \
        _Pragma("unroll") \
        for (int mt=0;mt<4;mt++){ \
            u32 ra = (Ab) + (wm*64+mt*16)*80 + ldm_off + k16*32; \
            ldm4(ah[mt], ra); \
            ldm4(al[mt], ra + 10240); \
        } \
        _Pragma("unroll") \
        for (int nt=0;nt<8;nt++){ \
            int off = ((k16*32 + wn*8 + nt)*64 + lane*2)*4; \
            uint2 bh = *(const uint2*)((Bb) + off); \
            uint2 bl = *(const uint2*)((Bb) + 16384 + off); \
            _Pragma("unroll") \
            for (int mt=0;mt<4;mt++){ \
                mma_f32(acc[mt][nt], ah[mt], bh.x, bh.y); \
                mma_f32(acc[mt][nt], ah[mt], bl.x, bl.y); \
                mma_f32(acc[mt][nt], al[mt], bh.x, bh.y); \
            } \
        } \
    }

// ===========================================================================
// Input conv. BM=128, BN=256, BK=32, 256 threads (8 warps, wm2 x wn4),
// warp tile 64x64, fp16x3 HMMA. Fused gate0 for t==0 images.
// ===========================================================================
template<int KH, int STRIDE, int CIN, bool HASBN>
__global__ void __launch_bounds__(256, 1)
conv_in(const float* __restrict__ in, ll in_str,
        const u32* __restrict__ wch, int NC,
        const float* __restrict__ biasP,
        const float* __restrict__ bns, const float* __restrict__ bnb,
        float* __restrict__ cbuf,
        float* __restrict__ outp, ll out_str,
        float* __restrict__ h0out, ll h0_str,
        int Hin, int Win, int Ho, int Wo)
{
    constexpr int PAD = (KH-1)/2;
    extern __shared__ char smem[];
    const u32 sb = smem_u32(smem);
    const int tid = threadIdx.x, wid = tid>>5, lane = tid&31;
    const int wm = wid>>2, wn = wid&3;
    const int HoWo = Ho*Wo;
    const int mblk = blockIdx.x << 7;

    const int arow = tid & 127, khalf = tid >> 7;
    const int am = mblk + arow;
    const int aimg = am / HoWo;
    const int ap = am - aimg*HoWo;
    const int oy = ap / Wo, ox = ap - (ap/Wo)*Wo;
    const float* inp = in + (ll)aimg*in_str;

    const int ldm_off = ((lane&7) + ((lane>>3)&1)*8)*80 + (lane>>4)*16;

    float acc[4][8][4];
    #pragma unroll
    for (int i=0;i<4;i++)
        #pragma unroll
        for (int j=0;j<8;j++)
            #pragma unroll
            for (int k=0;k<4;k++) acc[i][j][k]=0.f;

    auto gather = [&](int ic, float* v){
        #pragma unroll
        for (int e=0;e<16;e++) v[e]=0.f;
        const int kg = ic*32 + khalf*16;
        const int tap = kg / CIN;
        if (tap < KH*KH){
            const int ci = kg % CIN;
            const int ky = tap / KH, kx = tap - (tap/KH)*KH;
            const int iy = oy*STRIDE + ky - PAD;
            const int ix = ox*STRIDE + kx - PAD;
            if ((unsigned)iy < (unsigned)Hin && (unsigned)ix < (unsigned)Win){
                const float4* sp = (const float4*)(inp + ((ll)iy*Win+ix)*CIN + ci);
                #pragma unroll
                for (int q=0;q<4;q++){
                    float4 a = sp[q];
                    v[q*4+0]=a.x; v[q*4+1]=a.y; v[q*4+2]=a.z; v[q*4+3]=a.w;
                }
                if (HASBN){
                    const float BNRS = 0.9995003746877732f;
                    #pragma unroll
                    for (int e=0;e<16;e++)
                        v[e] = fmaf(v[e], __ldg(bns+ci+e)*BNRS, __ldg(bnb+ci+e));
                }
            }
        }
    };
    auto storeAc = [&](int s, const u32* c){
        char* base = smem + s*STG_BYTES + arow*80 + khalf*32;
        *(uint4*)base             = make_uint4(c[0],c[1],c[2],c[3]);
        *(uint4*)(base+16)        = make_uint4(c[4],c[5],c[6],c[7]);
        *(uint4*)(base+10240)     = make_uint4(c[8],c[9],c[10],c[11]);
        *(uint4*)(base+10240+16)  = make_uint4(c[12],c[13],c[14],c[15]);
    };
    auto copyB = [&](int ic, int s){
        const char* src = (const char*)(wch + (ll)ic*8192);
        u32 dstb = sb + s*STG_BYTES + 20480;
        #pragma unroll
        for (int i=0;i<8;i++)
            cpa16(dstb + tid*16 + i*4096, src + tid*16 + i*4096);
        CP_COMMIT();
    };

    u32 ca[16];
    {
        float v[16];
        gather(0, v); cvt16(v, ca);
        storeAc(0, ca);
        copyB(0, 0);
        CP_WAIT0();
        __syncthreads();
    }
    for (int ic=0; ic<NC; ic++){
        const int s = ic & 1;
        const bool more = (ic+1 < NC);
        float v[16];
        if (more){ copyB(ic+1, s^1); gather(ic+1, v); }
        {
            const u32 Ab = sb + s*STG_BYTES;
            const char* Bb = smem + s*STG_BYTES + 20480;
            COMPUTE_BODY(Ab, Bb)
        }
        if (more){ cvt16(v, ca); storeAc(s^1, ca); CP_WAIT0(); }
        __syncthreads();
    }

    // epilogue via SMEM (two 64-row halves)
    float* zsm = (float*)smem;   // [64][264]
    #pragma unroll
    for (int half=0; half<2; half++){
        if (wm == half){
            #pragma unroll
            for (int mt=0;mt<4;mt++){
                #pragma unroll
                for (int nt=0;nt<8;nt++){
                    int row = mt*16 + (lane>>2);
                    int col = wn*64 + nt*8 + (lane&3)*2;
                    *(float2*)&zsm[row*264 + col]     = make_float2(acc[mt][nt][0], acc[mt][nt][1]);
                    *(float2*)&zsm[(row+8)*264 + col] = make_float2(acc[mt][nt][2], acc[mt][nt][3]);
                }
            }
        }
        __syncthreads();
        {
            const int row = tid >> 2, fq = tid & 3;
            const int m = mblk + half*64 + row;
            const int img = m / HoWo;
            const int pix = m - img*HoWo;
            float* op = outp + (ll)img*out_str + (ll)pix*256 + fq*64;
            float4 o[16];
            #pragma unroll
            for (int j=0;j<16;j++){
                float4 q = *(float4*)&zsm[row*264 + fq*64 + j*4];
                float4 bv = *(const float4*)(biasP + fq*64 + j*4);
                o[j] = make_float4(q.x+bv.x, q.y+bv.y, q.z+bv.z, q.w+bv.w);
                *(float4*)(op + j*4) = o[j];
            }
            if ((img & 15) == 0){   // fused gate0 for t==0 images
                const int b = img >> 4;
                float* cp = cbuf + ((ll)b*HoWo + pix)*64 + fq*16;
                float* hp = h0out + (ll)b*h0_str + (ll)pix*64 + fq*16;
                #pragma unroll
                for (int j=0;j<16;j++){
                    float c = hsg(o[j].x)*fmaxf(o[j].z, 0.f);
                    stcg(cp + j, c);
                    hp[j] = hsg(o[j].w)*fmaxf(c, 0.f);
                }
            }
        }
        __syncthreads();
    }
}

// ===========================================================================
// Persistent recurrent conv with dependency-driven WORK STEALING.
// Items = (t, mtile), t in [1,15], dispatched topologically via atomic ctr.
// Item (t,m) waits on flags of (t-1, m-1..m+1) (halo <= 1 tile for KH<=5).
// grid = 148 (all SMs), no global barrier. c accessed via .cg (ownership
// migrates across blocks; L2 is the coherence point).
// ===========================================================================
template<int KH, int CIN>
__global__ void __launch_bounds__(256, 1)
conv_rec(const float* __restrict__ hbuf, ll H_Tp, ll H_IMGp,
         const u32* __restrict__ wch, int NC,
         const float* __restrict__ xzb, ll XZ_Tp, ll XZ_IMGp,
         float* __restrict__ cbuf, int TILES,
         int* __restrict__ flagb, int* __restrict__ ctr, int Ho, int Wo)
{
    constexpr int PAD = (KH-1)/2;
    extern __shared__ char smem[];
    const u32 sb = smem_u32(smem);
    int* ictl = (int*)(smem + 106496);
    const int tid = threadIdx.x, wid = tid>>5, lane = tid&31;
    const int wm = wid>>2, wn = wid&3;
    const int HoWo = Ho*Wo;
    const int arow = tid & 127, khalf = tid >> 7;
    const int ldm_off = ((lane&7) + ((lane>>3)&1)*8)*80 + (lane>>4)*16;
    const int erow = tid >> 2, efq = tid & 3;
    const int NITEM = 15*TILES;

    for (;;){
        if (tid == 0) ictl[0] = atomicAdd(ctr, 1);
        __syncthreads();
        const int item = ictl[0];
        if (item >= NITEM) break;
        const int t = item/TILES + 1;
        const int mtile = item - (t-1)*TILES;

        // wait for deps (t-1, mtile-1..mtile+1)
        if (t > 1){
            if (tid < 3){
                int mm = mtile + (int)tid - 1;
                mm = mm < 0 ? 0 : (mm >= TILES ? TILES-1 : mm);
                const int* fp = flagb + (ll)(t-2)*TILES + mm;
                u32 v;
                do {
                    asm volatile("ld.acquire.gpu.global.u32 %0, [%1];"
                                 : "=r"(v) : "l"(fp) : "memory");
                    if (!v) __nanosleep(64);
                } while (!v);
            }
        }
        __syncthreads();

        const int mblk = mtile << 7;
        const int am = mblk + arow;
        const int aimg = am / HoWo;
        const int ap = am - aimg*HoWo;
        const int oy = ap / Wo, ox = ap - (ap/Wo)*Wo;
        const float* inp = hbuf + (ll)(t-1)*H_Tp + (ll)aimg*H_IMGp;

        float acc[4][8][4];
        #pragma unroll
        for (int i=0;i<4;i++)
            #pragma unroll
            for (int j=0;j<8;j++)
                #pragma unroll
                for (int k=0;k<4;k++) acc[i][j][k]=0.f;

        auto gather = [&](int ic, float* v){
            #pragma unroll
            for (int e=0;e<16;e++) v[e]=0.f;
            const int kg = ic*32 + khalf*16;
            const int tap = kg / CIN;
            if (tap < KH*KH){
                const int ci = kg % CIN;
                const int ky = tap / KH, kx = tap - (tap/KH)*KH;
                const int iy = oy + ky - PAD;
                const int ix = ox + kx - PAD;
                if ((unsigned)iy < (unsigned)Ho && (unsigned)ix < (unsigned)Wo){
                    const float4* sp = (const float4*)(inp + ((ll)iy*Wo+ix)*CIN + ci);
                    #pragma unroll
                    for (int q=0;q<4;q++){
                        float4 a = sp[q];
                        v[q*4+0]=a.x; v[q*4+1]=a.y; v[q*4+2]=a.z; v[q*4+3]=a.w;
                    }
                }
            }
        };
        auto storeAc = [&](int s, const u32* c){
            char* base = smem + s*STG_BYTES + arow*80 + khalf*32;
            *(uint4*)base             = make_uint4(c[0],c[1],c[2],c[3]);
            *(uint4*)(base+16)        = make_uint4(c[4],c[5],c[6],c[7]);
            *(uint4*)(base+10240)     = make_uint4(c[8],c[9],c[10],c[11]);
            *(uint4*)(base+10240+16)  = make_uint4(c[12],c[13],c[14],c[15]);
        };
        auto copyB = [&](int ic, int s){
            const char* src = (const char*)(wch + (ll)ic*8192);
            u32 dstb = sb + s*STG_BYTES + 20480;
            #pragma unroll
            for (int i=0;i<8;i++)
                cpa16(dstb + tid*16 + i*4096, src + tid*16 + i*4096);
            CP_COMMIT();
        };

        u32 ca[16];
        {
            float v[16];
            gather(0, v); cvt16(v, ca);
            storeAc(0, ca);
            copyB(0, 0);
            CP_WAIT0();
            __syncthreads();
        }
        for (int ic=0; ic<NC; ic++){
            const int s = ic & 1;
            const bool more = (ic+1 < NC);
            float v[16];
            if (more){ copyB(ic+1, s^1); gather(ic+1, v); }
            {
                const u32 Ab = sb + s*STG_BYTES;
                const char* Bb = smem + s*STG_BYTES + 20480;
                COMPUTE_BODY(Ab, Bb)
            }
            if (more){ cvt16(v, ca); storeAc(s^1, ca); CP_WAIT0(); }
            __syncthreads();
        }

        // epilogue
        float* zsm = (float*)smem;
        #pragma unroll
        for (int half=0; half<2; half++){
            if (wm == half){
                #pragma unroll
                for (int mt=0;mt<4;mt++){
                    #pragma unroll
                    for (int nt=0;nt<8;nt++){
                        int row = mt*16 + (lane>>2);
                        int col = wn*64 + nt*8 + (lane&3)*2;
                        *(float2*)&zsm[row*264 + col]     = make_float2(acc[mt][nt][0], acc[mt][nt][1]);
                        *(float2*)&zsm[(row+8)*264 + col] = make_float2(acc[mt][nt][2], acc[mt][nt][3]);
                    }
                }
            }
            __syncthreads();
            {
                const int m = mblk + half*64 + erow;
                const int img = m / HoWo;
                const int pix = m - img*HoWo;
                const float* za = xzb + (ll)t*XZ_Tp + (ll)img*XZ_IMGp
                                  + (ll)pix*256 + efq*64;
                float* cp = cbuf + ((ll)img*HoWo + pix)*64 + efq*16;
                float* hp = (float*)(hbuf + (ll)t*H_Tp + (ll)img*H_IMGp
                                     + (ll)pix*64 + efq*16);
                #pragma unroll
                for (int j=0;j<16;j++){
                    float4 q = *(float4*)&zsm[erow*264 + efq*64 + j*4];
                    float4 x = *(const float4*)(za + j*4);
                    float zi = q.x + x.x, zf = q.y + x.y;
                    float zc = q.z + x.z, zo = q.w + x.w;
                    float co = ldcg(cp + j);
                    float c = hsg(zf)*co + hsg(zi)*fmaxf(zc,0.f);
                    stcg(cp + j, c);
                    hp[j] = hsg(zo)*fmaxf(c,0.f);
                }
            }
            __syncthreads();
        }

        // publish (t, mtile)
        __threadfence();
        if (tid == 0){
            asm volatile("st.release.gpu.global.u32 [%0], %1;"
                         :: "l"(flagb + (ll)(t-1)*TILES + mtile), "r"(1u) : "memory");
        }
        __syncthreads();
    }
}

// ---------------------------------------------------------------------------
// Conv3D 3x3x3 64->1 SAME + ReLU
// ---------------------------------------------------------------------------
__global__ void conv3d_kernel(const float* __restrict__ h, const float* __restrict__ w,
                              const float* __restrict__ b, float* __restrict__ out)
{
    const int idx = blockIdx.x*256 + threadIdx.x;
    if (idx >= BB*TT*32*32) return;
    const int x = idx & 31, y = (idx >> 5) & 31, t = (idx >> 10) & 15, bb = idx >> 14;
    float acc = __ldg(&b[0]);
    #pragma unroll
    for (int dt=-1; dt<=1; dt++){
        const int ti = t + dt;
        if ((unsigned)ti >= (unsigned)TT) continue;
        #pragma unroll
        for (int dy=-1; dy<=1; dy++){
            const int yi = y + dy;
            if ((unsigned)yi >= 32u) continue;
            #pragma unroll
            for (int dx=-1; dx<=1; dx++){
                const int xi = x + dx;
                if ((unsigned)xi >= 32u) continue;
                const float4* hp = (const float4*)(h + ((((ll)bb*TT+ti)*32+yi)*32+xi)*FF);
                const float4* wp = (const float4*)(w + (((dt+1)*3+(dy+1))*3+(dx+1))*FF);
                #pragma unroll
                for (int c4=0;c4<16;c4++){
                    float4 hv = hp[c4], wv = __ldg(&wp[c4]);
                    acc += hv.x*wv.x + hv.y*wv.y + hv.z*wv.z + hv.w*wv.w;
                }
            }
        }
    }
    out[idx] = fmaxf(acc, 0.f);
}

// ---------------------------------------------------------------------------
// Host
// ---------------------------------------------------------------------------
extern "C" void kernel_launch(void* const* d_in, const int* in_sizes, int n_in,
                              void* d_out, int out_size)
{
    const float* x   = (const float*)d_in[0];
    const float* k1  = (const float*)d_in[1];
    const float* rk1 = (const float*)d_in[2];
    const float* b1  = (const float*)d_in[3];
    const float* g1  = (const float*)d_in[4];
    const float* be1 = (const float*)d_in[5];
    const float* k2  = (const float*)d_in[6];
    const float* rk2 = (const float*)d_in[7];
    const float* b2  = (const float*)d_in[8];
    const float* g2  = (const float*)d_in[9];
    const float* be2 = (const float*)d_in[10];
    const float* k3  = (const float*)d_in[11];
    const float* rk3 = (const float*)d_in[12];
    const float* b3  = (const float*)d_in[13];
    const float* w3d = (const float*)d_in[14];
    const float* b3d = (const float*)d_in[15];
    float* out = (float*)d_out;

    float *xz, *ha, *hb, *h3, *cc, *pb;
    u32* wb;
    int *fl, *ct;
    cudaGetSymbolAddress((void**)&xz, g_xz);
    cudaGetSymbolAddress((void**)&ha, g_ha);
    cudaGetSymbolAddress((void**)&hb, g_hb);
    cudaGetSymbolAddress((void**)&h3, g_h3);
    cudaGetSymbolAddress((void**)&cc, g_c);
    cudaGetSymbolAddress((void**)&wb, g_wb32);
    cudaGetSymbolAddress((void**)&pb, g_pb);
    cudaGetSymbolAddress((void**)&fl, g_flag);
    cudaGetSymbolAddress((void**)&ct, g_ctr);

    auto* f1i = conv_in<5,1,16,false>;
    auto* f2i = conv_in<3,1,64,true>;
    auto* f3i = conv_in<1,2,64,true>;
    auto* r1  = conv_rec<5,64>;
    auto* r2  = conv_rec<3,64>;
    auto* r3  = conv_rec<1,64>;
    cudaFuncSetAttribute(f1i, cudaFuncAttributeMaxDynamicSharedMemorySize, SMEM_TOT);
    cudaFuncSetAttribute(f2i, cudaFuncAttributeMaxDynamicSharedMemorySize, SMEM_TOT);
    cudaFuncSetAttribute(f3i, cudaFuncAttributeMaxDynamicSharedMemorySize, SMEM_TOT);
    cudaFuncSetAttribute(r1,  cudaFuncAttributeMaxDynamicSharedMemorySize, SMEM_TOT);
    cudaFuncSetAttribute(r2,  cudaFuncAttributeMaxDynamicSharedMemorySize, SMEM_TOT);
    cudaFuncSetAttribute(r3,  cudaFuncAttributeMaxDynamicSharedMemorySize, SMEM_TOT);

    const ll X_IMG = (ll)HW*16;
    const ll XZ_IMG = (ll)TT*HW*256, XZ_T = (ll)HW*256;
    const ll H_IMG = (ll)TT*HW*FF,   H_T  = (ll)HW*FF;
    const ll XZ3_IMG = (ll)TT*HW3*256, XZ3_T = (ll)HW3*256;
    const ll H3_IMG = (ll)TT*HW3*FF,   H3_T  = (ll)HW3*FF;

    // Launch order keeps the profiler (local launch index 3) on r1.
    prep_all<<<1648, 256>>>(k1, rk1, k2, rk2, k3, rk3, wb);        // 0
    prep_misc<<<20, 256>>>(b1, b2, b3, pb);                        // 1

    // ============ Layer 1: ConvLSTM 5x5 ============
    f1i<<<2048, 256, SMEM_TOT>>>(x, X_IMG, wb+O1K, 13, pb,         // 2
        nullptr, nullptr, cc, xz, XZ_T, ha, H_IMG, HH, WW, HH, WW);
    r1<<<148, 256, SMEM_TOT>>>(ha, H_T, H_IMG, wb+O1R, 50,         // 3 <- profiled
        xz, XZ_T, XZ_IMG, cc, 128, fl, ct, HH, WW);

    // ============ Layer 2: ConvLSTM 3x3 (BN1 folded) ============
    f2i<<<2048, 256, SMEM_TOT>>>(ha, H_T, wb+O2K, 18, pb+256,
        g1, be1, cc, xz, XZ_T, hb, H_IMG, HH, WW, HH, WW);
    r2<<<148, 256, SMEM_TOT>>>(hb, H_T, H_IMG, wb+O2R, 18,
        xz, XZ_T, XZ_IMG, cc, 128, fl+1920, ct+1, HH, WW);

    // ============ Layer 3: ConvLSTM 1x1 stride 2 (BN2 folded) ============
    f3i<<<512, 256, SMEM_TOT>>>(hb, H_T, wb+O3K, 2, pb+512,
        g2, be2, cc, xz, XZ3_T, h3, H3_IMG, HH, WW, 32, 32);
    r3<<<148, 256, SMEM_TOT>>>(h3, H3_T, H3_IMG, wb+O3R, 2,
        xz, XZ3_T, XZ3_IMG, cc, 32, fl+3840, ct+2, 32, 32);

    conv3d_kernel<<<256, 256>>>(h3, w3d, b3d, out);
}

// round 16
// speedup vs baseline: 1.1952x; 1.1168x over previous
#include <cuda_runtime.h>
#include <cuda_fp16.h>

typedef unsigned int u32;
typedef long long ll;

#define BB 4
#define TT 16
#define HH 64
#define WW 64
#define FF 64
#define HW 4096
#define HW3 1024

__device__ float g_xz[(ll)BB*TT*HW*256];
__device__ float g_ha[(ll)BB*TT*HW*FF];
__device__ float g_hb[(ll)BB*TT*HW*FF];
__device__ float g_h3[(ll)BB*TT*HW3*FF];
__device__ float g_c [(ll)BB*HW*FF];
__device__ u32   g_wb32[843776];
__device__ float g_pb[768];
__device__ int   g_bar[64];

__device__ __forceinline__ float hsg(float x){ return fminf(fmaxf(fmaf(x,0.2f,0.5f),0.f),1.f); }
__device__ __forceinline__ u32 smem_u32(const void* p){
    u32 a;
    asm("{ .reg .u64 t; cvta.to.shared.u64 t, %1; cvt.u32.u64 %0, t; }":"=r"(a):"l"(p));
    return a;
}
__device__ __forceinline__ void cpa16(u32 s, const void* g){
    asm volatile("cp.async.cg.shared.global [%0], [%1], 16;"::"r"(s),"l"(g));
}
#define CP_COMMIT() asm volatile("cp.async.commit_group;")
#define CP_WAIT0()  asm volatile("cp.async.wait_group 0;" ::: "memory")
__device__ __forceinline__ void ldm4(u32* r, u32 a){
    asm volatile("ldmatrix.sync.aligned.m8n8.x4.shared.b16 {%0,%1,%2,%3}, [%4];"
        :"=r"(r[0]),"=r"(r[1]),"=r"(r[2]),"=r"(r[3]):"r"(a));
}
__device__ __forceinline__ void mma_f32(float* c, const u32* a, u32 b0, u32 b1){
    asm volatile("mma.sync.aligned.m16n8k16.row.col.f32.f16.f16.f32 "
        "{%0,%1,%2,%3}, {%4,%5,%6,%7}, {%8,%9}, {%0,%1,%2,%3};"
        : "+f"(c[0]),"+f"(c[1]),"+f"(c[2]),"+f"(c[3])
        : "r"(a[0]),"r"(a[1]),"r"(a[2]),"r"(a[3]),"r"(b0),"r"(b1));
}
// 16 fp32 -> 8 hi + 8 lo fp16x2 words
__device__ __forceinline__ void cvt16(const float* v, u32* c){
    #pragma unroll
    for (int e=0;e<8;e++){
        __half h0=__float2half_rn(v[2*e]),   h1=__float2half_rn(v[2*e+1]);
        __half l0=__float2half_rn(v[2*e]  -__half2float(h0));
        __half l1=__float2half_rn(v[2*e+1]-__half2float(h1));
        union { __half2 b; u32 x; } ph, pl;
        ph.b = __half2(h0,h1); pl.b = __half2(l0,l1);
        c[e]=ph.x; c[8+e]=pl.x;
    }
}

__device__ __forceinline__ void prep_one(const float* __restrict__ w,
                                         u32* __restrict__ dst, int K, int idx)
{
    int chunk = idx >> 12, r = idx & 4095;
    int k16 = r >> 11, t = r & 2047;
    int nt = t >> 6, u = t & 63;
    int lane = u >> 1, reg = u & 1;
    int pcol = nt*8 + (lane>>2);
    int f = pcol >> 2, g = pcol & 3;
    int n_orig = g*64 + f;
    int kg = chunk*32 + k16*16 + reg*8 + (lane&3)*2;
    float v0 = (kg   < K) ? w[(ll)kg*256 + n_orig] : 0.f;
    float v1 = (kg+1 < K) ? w[(ll)(kg+1)*256 + n_orig] : 0.f;
    __half h0 = __float2half_rn(v0), h1 = __float2half_rn(v1);
    __half l0 = __float2half_rn(v0 - __half2float(h0));
    __half l1 = __float2half_rn(v1 - __half2float(h1));
    union { __half2 b; u32 x; } ph, pl;
    ph.b = __half2(h0, h1);
    pl.b = __half2(l0, l1);
    dst[(ll)chunk*8192 + r]        = ph.x;
    dst[(ll)chunk*8192 + 4096 + r] = pl.x;
}

#define O1K 0
#define O1R 106496
#define O2K 516096
#define O2R 663552
#define O3K 811008
#define O3R 827392

__global__ void prep_all(const float* k1, const float* rk1, const float* k2,
                         const float* rk2, const float* k3, const float* rk3,
                         u32* __restrict__ wb)
{
    int gid = blockIdx.x*256 + threadIdx.x;
    if (gid >= 103*4096) return;
    int cg = gid >> 12;
    const float* w; u32* dst; int K, base;
    if      (cg < 13) { w = k1;  dst = wb+O1K; K = 400;  base = 0;   }
    else if (cg < 63) { w = rk1; dst = wb+O1R; K = 1600; base = 13;  }
    else if (cg < 81) { w = k2;  dst = wb+O2K; K = 576;  base = 63;  }
    else if (cg < 99) { w = rk2; dst = wb+O2R; K = 576;  base = 81;  }
    else if (cg < 101){ w = k3;  dst = wb+O3K; K = 64;   base = 99;  }
    else              { w = rk3; dst = wb+O3R; K = 64;   base = 101; }
    prep_one(w, dst, K, gid - base*4096);
}

__global__ void prep_misc(const float* b1, const float* b2, const float* b3,
                          float* __restrict__ pb)
{
    int i = threadIdx.x + blockIdx.x*256;
    if (i < 64) g_bar[i] = 0;
    if (i < 768){
        int l = i >> 8, pcol = i & 255;
        const float* b = (l==0) ? b1 : ((l==1) ? b2 : b3);
        pb[i] = b[(pcol&3)*64 + (pcol>>2)];
    }
}

#define STG_BYTES 53248
#define SMEM_TOT  106496

// 3-term body: a_hi*b_hi + a_hi*b_lo + a_lo*b_hi (fp32 accum)
#define COMPUTE3(Ab, Bb) \
    _Pragma("unroll") \
    for (int k16=0;k16<2;k16++){ \
        u32 ah[4][4], al[4][4]; \
        _Pragma("unroll") \
        for (int mt=0;mt<4;mt++){ \
            u32 ra = (Ab) + (wm*64+mt*16)*80 + ldm_off + k16*32; \
            ldm4(ah[mt], ra); \
            ldm4(al[mt], ra + 10240); \
        } \
        _Pragma("unroll") \
        for (int nt=0;nt<8;nt++){ \
            int off = ((k16*32 + wn*8 + nt)*64 + lane*2)*4; \
            uint2 bh = *(const uint2*)((Bb) + off); \
            uint2 bl = *(const uint2*)((Bb) + 16384 + off); \
            _Pragma("unroll") \
            for (int mt=0;mt<4;mt++){ \
                mma_f32(acc[mt][nt], ah[mt], bh.x, bh.y); \
                mma_f32(acc[mt][nt], ah[mt], bl.x, bl.y); \
                mma_f32(acc[mt][nt], al[mt], bh.x, bh.y); \
            } \
        } \
    }

// ===========================================================================
// Input conv: BM=128, BN=256, BK=32, 256 threads, 64x64 warp tiles, fp16x3.
// Fused gate0 for t==0 images.
// ===========================================================================
template<int KH, int STRIDE, int CIN, bool HASBN>
__global__ void __launch_bounds__(256, 1)
conv_in(const float* __restrict__ in, ll in_str,
        const u32* __restrict__ wch, int NC,
        const float* __restrict__ biasP,
        const float* __restrict__ bns, const float* __restrict__ bnb,
        float* __restrict__ cbuf,
        float* __restrict__ outp, ll out_str,
        float* __restrict__ h0out, ll h0_str,
        int Hin, int Win, int Ho, int Wo)
{
    constexpr int PAD = (KH-1)/2;
    extern __shared__ char smem[];
    const u32 sb = smem_u32(smem);
    const int tid = threadIdx.x, wid = tid>>5, lane = tid&31;
    const int wm = wid>>2, wn = wid&3;
    const int HoWo = Ho*Wo;
    const int mblk = blockIdx.x << 7;

    const int arow = tid & 127, khalf = tid >> 7;
    const int am = mblk + arow;
    const int aimg = am / HoWo;
    const int ap = am - aimg*HoWo;
    const int oy = ap / Wo, ox = ap - (ap/Wo)*Wo;
    const float* inp = in + (ll)aimg*in_str;

    const int ldm_off = ((lane&7) + ((lane>>3)&1)*8)*80 + (lane>>4)*16;

    float acc[4][8][4];
    #pragma unroll
    for (int i=0;i<4;i++)
        #pragma unroll
        for (int j=0;j<8;j++)
            #pragma unroll
            for (int k=0;k<4;k++) acc[i][j][k]=0.f;

    auto gather = [&](int ic, float* v){
        #pragma unroll
        for (int e=0;e<16;e++) v[e]=0.f;
        const int kg = ic*32 + khalf*16;
        const int tap = kg / CIN;
        if (tap < KH*KH){
            const int ci = kg % CIN;
            const int ky = tap / KH, kx = tap - (tap/KH)*KH;
            const int iy = oy*STRIDE + ky - PAD;
            const int ix = ox*STRIDE + kx - PAD;
            if ((unsigned)iy < (unsigned)Hin && (unsigned)ix < (unsigned)Win){
                const float4* sp = (const float4*)(inp + ((ll)iy*Win+ix)*CIN + ci);
                #pragma unroll
                for (int q=0;q<4;q++){
                    float4 a = sp[q];
                    v[q*4+0]=a.x; v[q*4+1]=a.y; v[q*4+2]=a.z; v[q*4+3]=a.w;
                }
                if (HASBN){
                    const float BNRS = 0.9995003746877732f;
                    #pragma unroll
                    for (int e=0;e<16;e++)
                        v[e] = fmaf(v[e], __ldg(bns+ci+e)*BNRS, __ldg(bnb+ci+e));
                }
            }
        }
    };
    auto storeAc = [&](int s, const u32* c){
        char* base = smem + s*STG_BYTES + arow*80 + khalf*32;
        *(uint4*)base             = make_uint4(c[0],c[1],c[2],c[3]);
        *(uint4*)(base+16)        = make_uint4(c[4],c[5],c[6],c[7]);
        *(uint4*)(base+10240)     = make_uint4(c[8],c[9],c[10],c[11]);
        *(uint4*)(base+10240+16)  = make_uint4(c[12],c[13],c[14],c[15]);
    };
    auto copyB = [&](int ic, int s){
        const char* src = (const char*)(wch + (ll)ic*8192);
        u32 dstb = sb + s*STG_BYTES + 20480;
        #pragma unroll
        for (int i=0;i<8;i++)
            cpa16(dstb + tid*16 + i*4096, src + tid*16 + i*4096);
        CP_COMMIT();
    };

    u32 ca[16];
    {
        float v[16];
        gather(0, v); cvt16(v, ca);
        storeAc(0, ca);
        copyB(0, 0);
        CP_WAIT0();
        __syncthreads();
    }
    for (int ic=0; ic<NC; ic++){
        const int s = ic & 1;
        const bool more = (ic+1 < NC);
        float v[16];
        if (more){ copyB(ic+1, s^1); gather(ic+1, v); }
        {
            const u32 Ab = sb + s*STG_BYTES;
            const char* Bb = smem + s*STG_BYTES + 20480;
            COMPUTE3(Ab, Bb)
        }
        if (more){ cvt16(v, ca); storeAc(s^1, ca); CP_WAIT0(); }
        __syncthreads();
    }

    float* zsm = (float*)smem;   // [64][264]
    #pragma unroll
    for (int half=0; half<2; half++){
        if (wm == half){
            #pragma unroll
            for (int mt=0;mt<4;mt++){
                #pragma unroll
                for (int nt=0;nt<8;nt++){
                    int row = mt*16 + (lane>>2);
                    int col = wn*64 + nt*8 + (lane&3)*2;
                    *(float2*)&zsm[row*264 + col]     = make_float2(acc[mt][nt][0], acc[mt][nt][1]);
                    *(float2*)&zsm[(row+8)*264 + col] = make_float2(acc[mt][nt][2], acc[mt][nt][3]);
                }
            }
        }
        __syncthreads();
        {
            const int row = tid >> 2, fq = tid & 3;
            const int m = mblk + half*64 + row;
            const int img = m / HoWo;
            const int pix = m - img*HoWo;
            float* op = outp + (ll)img*out_str + (ll)pix*256 + fq*64;
            float4 o[16];
            #pragma unroll
            for (int j=0;j<16;j++){
                float4 q = *(float4*)&zsm[row*264 + fq*64 + j*4];
                float4 bv = *(const float4*)(biasP + fq*64 + j*4);
                o[j] = make_float4(q.x+bv.x, q.y+bv.y, q.z+bv.z, q.w+bv.w);
                *(float4*)(op + j*4) = o[j];
            }
            if ((img & 15) == 0){
                const int b = img >> 4;
                float cn[16], ho[16];
                #pragma unroll
                for (int j=0;j<16;j++){
                    float c = hsg(o[j].x)*fmaxf(o[j].z, 0.f);
                    cn[j] = c;
                    ho[j] = hsg(o[j].w)*fmaxf(c, 0.f);
                }
                float* cp = cbuf + ((ll)b*HoWo + pix)*64 + fq*16;
                float* hp = h0out + (ll)b*h0_str + (ll)pix*64 + fq*16;
                #pragma unroll
                for (int g=0; g<4; g++){
                    *(float4*)(cp + g*4) = *(float4*)&cn[g*4];
                    *(float4*)(hp + g*4) = *(float4*)&ho[g*4];
                }
            }
        }
        __syncthreads();
    }
}

// ===========================================================================
// Persistent recurrent conv, fp16x3, per-step software grid barrier.
// ===========================================================================
template<int KH, int CIN>
__global__ void __launch_bounds__(256, 1)
conv_rec(const float* __restrict__ hbuf, ll H_Tp, ll H_IMGp,
         const u32* __restrict__ wch, int NC,
         const float* __restrict__ xzb, ll XZ_Tp, ll XZ_IMGp,
         float* __restrict__ cbuf, int nstep, int barbase, int Ho, int Wo)
{
    constexpr int PAD = (KH-1)/2;
    extern __shared__ char smem[];
    const u32 sb = smem_u32(smem);
    const int tid = threadIdx.x, wid = tid>>5, lane = tid&31;
    const int wm = wid>>2, wn = wid&3;
    const int HoWo = Ho*Wo;
    const int mblk = blockIdx.x << 7;
    const int nblk = gridDim.x;

    const int arow = tid & 127, khalf = tid >> 7;
    const int am = mblk + arow;
    const int aimg = am / HoWo;
    const int ap = am - aimg*HoWo;
    const int oy = ap / Wo, ox = ap - (ap/Wo)*Wo;

    const int ldm_off = ((lane&7) + ((lane>>3)&1)*8)*80 + (lane>>4)*16;
    const int erow = tid >> 2, efq = tid & 3;

    for (int t = 1; t <= nstep; t++){
        const float* inp = hbuf + (ll)(t-1)*H_Tp + (ll)aimg*H_IMGp;

        float acc[4][8][4];
        #pragma unroll
        for (int i=0;i<4;i++)
            #pragma unroll
            for (int j=0;j<8;j++)
                #pragma unroll
                for (int k=0;k<4;k++) acc[i][j][k]=0.f;

        auto gather = [&](int ic, float* v){
            #pragma unroll
            for (int e=0;e<16;e++) v[e]=0.f;
            const int kg = ic*32 + khalf*16;
            const int tap = kg / CIN;
            if (tap < KH*KH){
                const int ci = kg % CIN;
                const int ky = tap / KH, kx = tap - (tap/KH)*KH;
                const int iy = oy + ky - PAD;
                const int ix = ox + kx - PAD;
                if ((unsigned)iy < (unsigned)Ho && (unsigned)ix < (unsigned)Wo){
                    const float4* sp = (const float4*)(inp + ((ll)iy*Wo+ix)*CIN + ci);
                    #pragma unroll
                    for (int q=0;q<4;q++){
                        float4 a = sp[q];
                        v[q*4+0]=a.x; v[q*4+1]=a.y; v[q*4+2]=a.z; v[q*4+3]=a.w;
                    }
                }
            }
        };
        auto storeAc = [&](int s, const u32* c){
            char* base = smem + s*STG_BYTES + arow*80 + khalf*32;
            *(uint4*)base             = make_uint4(c[0],c[1],c[2],c[3]);
            *(uint4*)(base+16)        = make_uint4(c[4],c[5],c[6],c[7]);
            *(uint4*)(base+10240)     = make_uint4(c[8],c[9],c[10],c[11]);
            *(uint4*)(base+10240+16)  = make_uint4(c[12],c[13],c[14],c[15]);
        };
        auto copyB = [&](int ic, int s){
            const char* src = (const char*)(wch + (ll)ic*8192);
            u32 dstb = sb + s*STG_BYTES + 20480;
            #pragma unroll
            for (int i=0;i<8;i++)
                cpa16(dstb + tid*16 + i*4096, src + tid*16 + i*4096);
            CP_COMMIT();
        };

        u32 ca[16];
        {
            float v[16];
            gather(0, v); cvt16(v, ca);
            storeAc(0, ca);
            copyB(0, 0);
            CP_WAIT0();
            __syncthreads();
        }
        for (int ic=0; ic<NC; ic++){
            const int s = ic & 1;
            const bool more = (ic+1 < NC);
            float v[16];
            if (more){ copyB(ic+1, s^1); gather(ic+1, v); }
            {
                const u32 Ab = sb + s*STG_BYTES;
                const char* Bb = smem + s*STG_BYTES + 20480;
                COMPUTE3(Ab, Bb)
            }
            if (more){ cvt16(v, ca); storeAc(s^1, ca); CP_WAIT0(); }
            __syncthreads();
        }

        float* zsm = (float*)smem;
        #pragma unroll
        for (int half=0; half<2; half++){
            if (wm == half){
                #pragma unroll
                for (int mt=0;mt<4;mt++){
                    #pragma unroll
                    for (int nt=0;nt<8;nt++){
                        int row = mt*16 + (lane>>2);
                        int col = wn*64 + nt*8 + (lane&3)*2;
                        *(float2*)&zsm[row*264 + col]     = make_float2(acc[mt][nt][0], acc[mt][nt][1]);
                        *(float2*)&zsm[(row+8)*264 + col] = make_float2(acc[mt][nt][2], acc[mt][nt][3]);
                    }
                }
            }
            __syncthreads();
            {
                const int m = mblk + half*64 + erow;
                const int img = m / HoWo;
                const int pix = m - img*HoWo;
                const float* za = xzb + (ll)t*XZ_Tp + (ll)img*XZ_IMGp
                                  + (ll)pix*256 + efq*64;
                float* cp = cbuf + ((ll)img*HoWo + pix)*64 + efq*16;
                float* hp = (float*)(hbuf + (ll)t*H_Tp + (ll)img*H_IMGp
                                     + (ll)pix*64 + efq*16);
                float co[16], cn[16], ho[16];
                #pragma unroll
                for (int g=0; g<4; g++)
                    *(float4*)&co[g*4] = *(const float4*)(cp + g*4);
                #pragma unroll
                for (int j=0;j<16;j++){
                    float4 q = *(float4*)&zsm[erow*264 + efq*64 + j*4];
                    float4 x = *(const float4*)(za + j*4);
                    float zi = q.x + x.x, zf = q.y + x.y;
                    float zc = q.z + x.z, zo = q.w + x.w;
                    float c = hsg(zf)*co[j] + hsg(zi)*fmaxf(zc,0.f);
                    cn[j] = c; ho[j] = hsg(zo)*fmaxf(c,0.f);
                }
                #pragma unroll
                for (int g=0; g<4; g++){
                    *(float4*)(cp + g*4) = *(float4*)&cn[g*4];
                    *(float4*)(hp + g*4) = *(float4*)&ho[g*4];
                }
            }
            __syncthreads();
        }

        if (t < nstep){
            __threadfence();
            __syncthreads();
            if (tid == 0){
                int* bp = &g_bar[barbase + t];
                atomicAdd(bp, 1);
                u32 v;
                do {
                    asm volatile("ld.acquire.gpu.global.u32 %0, [%1];"
                                 : "=r"(v) : "l"(bp) : "memory");
                    if (v < (u32)nblk) __nanosleep(128);
                } while (v < (u32)nblk);
            }
            __syncthreads();
        }
    }
}

__global__ void conv3d_kernel(const float* __restrict__ h, const float* __restrict__ w,
                              const float* __restrict__ b, float* __restrict__ out)
{
    const int idx = blockIdx.x*256 + threadIdx.x;
    if (idx >= BB*TT*32*32) return;
    const int x = idx & 31, y = (idx >> 5) & 31, t = (idx >> 10) & 15, bb = idx >> 14;
    float acc = __ldg(&b[0]);
    #pragma unroll
    for (int dt=-1; dt<=1; dt++){
        const int ti = t + dt;
        if ((unsigned)ti >= (unsigned)TT) continue;
        #pragma unroll
        for (int dy=-1; dy<=1; dy++){
            const int yi = y + dy;
            if ((unsigned)yi >= 32u) continue;
            #pragma unroll
            for (int dx=-1; dx<=1; dx++){
                const int xi = x + dx;
                if ((unsigned)xi >= 32u) continue;
                const float4* hp = (const float4*)(h + ((((ll)bb*TT+ti)*32+yi)*32+xi)*FF);
                const float4* wp = (const float4*)(w + (((dt+1)*3+(dy+1))*3+(dx+1))*FF);
                #pragma unroll
                for (int c4=0;c4<16;c4++){
                    float4 hv = hp[c4], wv = __ldg(&wp[c4]);
                    acc += hv.x*wv.x + hv.y*wv.y + hv.z*wv.z + hv.w*wv.w;
                }
            }
        }
    }
    out[idx] = fmaxf(acc, 0.f);
}

extern "C" void kernel_launch(void* const* d_in, const int* in_sizes, int n_in,
                              void* d_out, int out_size)
{
    const float* x   = (const float*)d_in[0];
    const float* k1  = (const float*)d_in[1];
    const float* rk1 = (const float*)d_in[2];
    const float* b1  = (const float*)d_in[3];
    const float* g1  = (const float*)d_in[4];
    const float* be1 = (const float*)d_in[5];
    const float* k2  = (const float*)d_in[6];
    const float* rk2 = (const float*)d_in[7];
    const float* b2  = (const float*)d_in[8];
    const float* g2  = (const float*)d_in[9];
    const float* be2 = (const float*)d_in[10];
    const float* k3  = (const float*)d_in[11];
    const float* rk3 = (const float*)d_in[12];
    const float* b3  = (const float*)d_in[13];
    const float* w3d = (const float*)d_in[14];
    const float* b3d = (const float*)d_in[15];
    float* out = (float*)d_out;

    float *xz, *ha, *hb, *h3, *cc, *pb;
    u32* wb;
    cudaGetSymbolAddress((void**)&xz, g_xz);
    cudaGetSymbolAddress((void**)&ha, g_ha);
    cudaGetSymbolAddress((void**)&hb, g_hb);
    cudaGetSymbolAddress((void**)&h3, g_h3);
    cudaGetSymbolAddress((void**)&cc, g_c);
    cudaGetSymbolAddress((void**)&wb, g_wb32);
    cudaGetSymbolAddress((void**)&pb, g_pb);

    auto* f1i = conv_in<5,1,16,false>;
    auto* f2i = conv_in<3,1,64,true>;
    auto* f3i = conv_in<1,2,64,true>;
    auto* r1  = conv_rec<5,64>;
    auto* r2  = conv_rec<3,64>;
    auto* r3  = conv_rec<1,64>;
    cudaFuncSetAttribute(f1i, cudaFuncAttributeMaxDynamicSharedMemorySize, SMEM_TOT);
    cudaFuncSetAttribute(f2i, cudaFuncAttributeMaxDynamicSharedMemorySize, SMEM_TOT);
    cudaFuncSetAttribute(f3i, cudaFuncAttributeMaxDynamicSharedMemorySize, SMEM_TOT);
    cudaFuncSetAttribute(r1,  cudaFuncAttributeMaxDynamicSharedMemorySize, SMEM_TOT);
    cudaFuncSetAttribute(r2,  cudaFuncAttributeMaxDynamicSharedMemorySize, SMEM_TOT);
    cudaFuncSetAttribute(r3,  cudaFuncAttributeMaxDynamicSharedMemorySize, SMEM_TOT);

    const ll X_IMG = (ll)HW*16;
    const ll XZ_IMG = (ll)TT*HW*256, XZ_T = (ll)HW*256;
    const ll H_IMG = (ll)TT*HW*FF,   H_T  = (ll)HW*FF;
    const ll XZ3_IMG = (ll)TT*HW3*256, XZ3_T = (ll)HW3*256;
    const ll H3_IMG = (ll)TT*HW3*FF,   H3_T  = (ll)HW3*FF;

    prep_all<<<1648, 256>>>(k1, rk1, k2, rk2, k3, rk3, wb);
    prep_misc<<<3, 256>>>(b1, b2, b3, pb);

    f1i<<<2048, 256, SMEM_TOT>>>(x, X_IMG, wb+O1K, 13, pb,
        nullptr, nullptr, cc, xz, XZ_T, ha, H_IMG, HH, WW, HH, WW);
    r1<<<128, 256, SMEM_TOT>>>(ha, H_T, H_IMG, wb+O1R, 50,
        xz, XZ_T, XZ_IMG, cc, 15, 0, HH, WW);

    f2i<<<2048, 256, SMEM_TOT>>>(ha, H_T, wb+O2K, 18, pb+256,
        g1, be1, cc, xz, XZ_T, hb, H_IMG, HH, WW, HH, WW);
    r2<<<128, 256, SMEM_TOT>>>(hb, H_T, H_IMG, wb+O2R, 18,
        xz, XZ_T, XZ_IMG, cc, 15, 16, HH, WW);

    f3i<<<512, 256, SMEM_TOT>>>(hb, H_T, wb+O3K, 2, pb+512,
        g2, be2, cc, xz, XZ3_T, h3, H3_IMG, HH, WW, 32, 32);
    r3<<<32, 256, SMEM_TOT>>>(h3, H3_T, H3_IMG, wb+O3R, 2,
        xz, XZ3_T, XZ3_IMG, cc, 15, 32, 32, 32);

    conv3d_kernel<<<256, 256>>>(h3, w3d, b3d, out);
}